// round 2
// baseline (speedup 1.0000x reference)
#include <cuda_runtime.h>
#include <math.h>

#define BATCH 8
#define NPTS  2048
#define LOG2E 1.4426950408889634f
#define LN2   0.6931471805599453f
#define TPB   128

// dual potentials, double-buffered: [buf][which: f_ba,g_ab,f_aa,g_bb][b*NPTS + i]
__device__ float g_dual[2][4][BATCH * NPTS];

__device__ __forceinline__ float ex2(float x) {
    float r;
    asm("ex2.approx.ftz.f32 %0, %1;" : "=f"(r) : "f"(x));
    return r;
}

// One "phase" = 4 independent softmins (selected by blockIdx.y) over all batches.
//   s=0: f_ba  rows=x cols=y  dual=g_ab
//   s=1: g_ab  rows=y cols=x  dual=f_ba
//   s=2: f_aa  rows=x cols=x  dual=f_aa
//   s=3: g_bb  rows=y cols=y  dual=g_bb
// softmin(eps,C,h)_i = -eps * LSE_j( h_j - C_ij/eps ),  C_ij = 0.5|x_i|^2 + 0.5|y_j|^2 - x.y
// Work in log2 domain: arg2_j = (h_j - 0.5|c_j|^2/eps)*log2e + x_i.c_j*(log2e/eps)
// softmin_i = -eps*LN2*(m + log2(sum)) + 0.5|x_i|^2
__global__ __launch_bounds__(TPB) void sinkhorn_phase(
    const float* __restrict__ x, const float* __restrict__ y,
    float eps, float dual_scale, int do_avg, int rbuf, int wbuf)
{
    const int s = blockIdx.y;
    const int b = blockIdx.z;
    const float* rows = (s == 0 || s == 2) ? x : y;
    const float* cols = (s == 0 || s == 3) ? y : x;
    const int dual_idx = (s == 0) ? 1 : (s == 1) ? 0 : s;
    const float* dual = g_dual[rbuf][dual_idx] + b * NPTS;
    const float* own  = g_dual[rbuf][s]        + b * NPTS;
    float*       out  = g_dual[wbuf][s]        + b * NPTS;

    __shared__ float4 sh[NPTS];   // (c0,c1,c2)*inv_eps*log2e, hb*log2e

    const float inv_eps = 1.0f / eps;
    const float sc = inv_eps * LOG2E;
    const float logw = -logf((float)NPTS);

    // build column table (y/x points + per-column log-weight term)
    for (int j = threadIdx.x; j < NPTS; j += TPB) {
        const float* c = cols + (b * NPTS + j) * 3;
        float c0 = c[0], c1 = c[1], c2 = c[2];
        float h = logw + dual_scale * dual[j] * inv_eps;
        float hb = (h - 0.5f * (c0 * c0 + c1 * c1 + c2 * c2) * inv_eps) * LOG2E;
        sh[j] = make_float4(c0 * sc, c1 * sc, c2 * sc, hb);
    }
    __syncthreads();

    const int r = blockIdx.x * TPB + threadIdx.x;
    const float* xr = rows + (b * NPTS + r) * 3;
    const float x0 = xr[0], x1 = xr[1], x2 = xr[2];

    float m = -INFINITY;
    float ssum = 0.0f;

    #pragma unroll 1
    for (int j = 0; j < NPTS; j += 8) {
        float a[8];
        #pragma unroll
        for (int k = 0; k < 8; k++) {
            float4 v = sh[j + k];
            a[k] = fmaf(x0, v.x, fmaf(x1, v.y, fmaf(x2, v.z, v.w)));
        }
        float cm = fmaxf(fmaxf(fmaxf(a[0], a[1]), fmaxf(a[2], a[3])),
                         fmaxf(fmaxf(a[4], a[5]), fmaxf(a[6], a[7])));
        if (cm > m) {               // rare after warm-up
            ssum *= ex2(m - cm);    // ex2(-inf)=0 handles first chunk
            m = cm;
        }
        float e0 = ex2(a[0] - m) + ex2(a[1] - m);
        float e1 = ex2(a[2] - m) + ex2(a[3] - m);
        float e2 = ex2(a[4] - m) + ex2(a[5] - m);
        float e3 = ex2(a[6] - m) + ex2(a[7] - m);
        ssum += (e0 + e1) + (e2 + e3);
    }

    float lse = LN2 * (m + log2f(ssum));
    float sq = 0.5f * (x0 * x0 + x1 * x1 + x2 * x2);
    float fraw = -eps * lse + sq;
    out[r] = do_avg ? 0.5f * (own[r] + fraw) : fraw;
}

// out[b] = (1/N) * sum_i (f_ba - f_aa) + (1/M) * sum_j (g_ab - g_bb)
__global__ void sinkhorn_reduce(float* __restrict__ out, int buf)
{
    const int b = blockIdx.x;
    const int tid = threadIdx.x;
    float acc = 0.0f;
    for (int i = tid; i < NPTS; i += 256) {
        acc += g_dual[buf][0][b * NPTS + i] - g_dual[buf][2][b * NPTS + i];
        acc += g_dual[buf][1][b * NPTS + i] - g_dual[buf][3][b * NPTS + i];
    }
    // block reduction
    __shared__ float red[256];
    red[tid] = acc;
    __syncthreads();
    for (int off = 128; off > 0; off >>= 1) {
        if (tid < off) red[tid] += red[tid + off];
        __syncthreads();
    }
    if (tid == 0) {
        float w = expf(-logf((float)NPTS));   // match jnp.exp(a_log)
        out[b] = red[0] * w;
    }
}

extern "C" void kernel_launch(void* const* d_in, const int* in_sizes, int n_in,
                              void* d_out, int out_size)
{
    const float* x = (const float*)d_in[0];
    const float* y = (const float*)d_in[1];
    float* out = (float*)d_out;

    dim3 grid(NPTS / TPB, 4, BATCH);

    // epsilon schedule: [diameter^2] + exp(arange(2ln2, 2ln0.05, 2ln0.5)) + [blur^2]
    const float eps_list[8] = {4.0f, 4.0f, 1.0f, 0.25f, 0.0625f,
                               0.015625f, 0.00390625f, 0.0025f};

    // init at eps0=4 (h = log-weights only), write buf0
    sinkhorn_phase<<<grid, TPB>>>(x, y, 4.0f, 0.0f, 0, 0, 0);

    int cur = 0;
    for (int i = 0; i < 8; i++) {
        sinkhorn_phase<<<grid, TPB>>>(x, y, eps_list[i], 1.0f, 1, cur, cur ^ 1);
        cur ^= 1;
    }
    // final extrapolation at blur^2, no averaging
    sinkhorn_phase<<<grid, TPB>>>(x, y, 0.0025f, 1.0f, 0, cur, cur ^ 1);
    cur ^= 1;

    sinkhorn_reduce<<<BATCH, 256>>>(out, cur);
}

// round 5
// speedup vs baseline: 1.0113x; 1.0113x over previous
#include <cuda_runtime.h>
#include <math.h>

#define BATCH 8
#define NPTS  2048
#define LOG2E 1.4426950408889634f
#define LN2   0.6931471805599453f
#define TPB   128
#define CHUNK 16

// dual potentials, double-buffered: [buf][which: f_ba,g_ab,f_aa,g_bb][b*NPTS + i]
__device__ float g_dual[2][4][BATCH * NPTS];

__device__ __forceinline__ float ex2(float x) {
    float r;
    asm("ex2.approx.ftz.f32 %0, %1;" : "=f"(r) : "f"(x));
    return r;
}

// One "phase" = 4 independent softmins (selected by blockIdx.y) over all batches.
//   s=0: f_ba  rows=x cols=y  dual=g_ab
//   s=1: g_ab  rows=y cols=x  dual=f_ba
//   s=2: f_aa  rows=x cols=x  dual=f_aa
//   s=3: g_bb  rows=y cols=y  dual=g_bb
// softmin(eps,C,h)_i = -eps * LSE_j( h_j - C_ij/eps ),  C_ij = 0.5|x_i|^2 + 0.5|y_j|^2 - x.y
// log2 domain: arg2_j = (h_j - 0.5|c_j|^2/eps)*log2e + x_i.c_j*(log2e/eps)
// softmin_i = -eps*LN2*(m + log2(sum)) + 0.5|x_i|^2
__global__ __launch_bounds__(TPB) void sinkhorn_phase(
    const float* __restrict__ x, const float* __restrict__ y,
    float eps, float dual_scale, int do_avg, int rbuf, int wbuf)
{
    const int s = blockIdx.y;
    const int b = blockIdx.z;
    const float* rows = (s == 0 || s == 2) ? x : y;
    const float* cols = (s == 0 || s == 3) ? y : x;
    const int dual_idx = (s == 0) ? 1 : (s == 1) ? 0 : s;
    const float* dual = g_dual[rbuf][dual_idx] + b * NPTS;
    const float* own  = g_dual[rbuf][s]        + b * NPTS;
    float*       out  = g_dual[wbuf][s]        + b * NPTS;

    __shared__ float4 sh[NPTS];   // (c0,c1,c2)*inv_eps*log2e, hb (log2 units)

    const float inv_eps = 1.0f / eps;
    const float sc = inv_eps * LOG2E;
    const float logw = -logf((float)NPTS);

    // build column table
    for (int j = threadIdx.x; j < NPTS; j += TPB) {
        const float* c = cols + (b * NPTS + j) * 3;
        float c0 = c[0], c1 = c[1], c2 = c[2];
        float h = logw + dual_scale * dual[j] * inv_eps;
        float hb = (h - 0.5f * (c0 * c0 + c1 * c1 + c2 * c2) * inv_eps) * LOG2E;
        sh[j] = make_float4(c0 * sc, c1 * sc, c2 * sc, hb);
    }
    __syncthreads();

    const int r = blockIdx.x * TPB + threadIdx.x;
    const float* xr = rows + (b * NPTS + r) * 3;
    const float x0 = xr[0], x1 = xr[1], x2 = xr[2];

    float m = -INFINITY;
    float ssum = 0.0f;

    #pragma unroll 1
    for (int j = 0; j < NPTS; j += CHUNK) {
        float a[CHUNK];
        #pragma unroll
        for (int k = 0; k < CHUNK; k++) {
            float4 v = sh[j + k];
            a[k] = fmaf(x0, v.x, fmaf(x1, v.y, fmaf(x2, v.z, v.w)));
        }
        // chunk-local max (tree, depth 4)
        float t0 = fmaxf(a[0], a[1]),   t1 = fmaxf(a[2], a[3]);
        float t2 = fmaxf(a[4], a[5]),   t3 = fmaxf(a[6], a[7]);
        float t4 = fmaxf(a[8], a[9]),   t5 = fmaxf(a[10], a[11]);
        float t6 = fmaxf(a[12], a[13]), t7 = fmaxf(a[14], a[15]);
        float u0 = fmaxf(t0, t1), u1 = fmaxf(t2, t3);
        float u2 = fmaxf(t4, t5), u3 = fmaxf(t6, t7);
        float cm = fmaxf(fmaxf(u0, u1), fmaxf(u2, u3));

        // exps relative to chunk max (independent of running state -> pipelines)
        float e[CHUNK];
        #pragma unroll
        for (int k = 0; k < CHUNK; k++) e[k] = ex2(a[k] - cm);
        float s0 = (e[0] + e[1]) + (e[2] + e[3]);
        float s1 = (e[4] + e[5]) + (e[6] + e[7]);
        float s2 = (e[8] + e[9]) + (e[10] + e[11]);
        float s3 = (e[12] + e[13]) + (e[14] + e[15]);
        float csum = (s0 + s1) + (s2 + s3);

        // branchless merge; one of the two ex2 args is exactly 0
        float mn = fmaxf(m, cm);
        ssum = fmaf(ssum, ex2(m - mn), csum * ex2(cm - mn));
        m = mn;
    }

    float lse = LN2 * (m + log2f(ssum));
    float sq = 0.5f * (x0 * x0 + x1 * x1 + x2 * x2);
    float fraw = -eps * lse + sq;
    out[r] = do_avg ? 0.5f * (own[r] + fraw) : fraw;
}

// out[b] = (1/N) * sum_i (f_ba - f_aa) + (1/M) * sum_j (g_ab - g_bb)
__global__ void sinkhorn_reduce(float* __restrict__ out, int buf)
{
    const int b = blockIdx.x;
    const int tid = threadIdx.x;
    float acc = 0.0f;
    for (int i = tid; i < NPTS; i += 256) {
        acc += g_dual[buf][0][b * NPTS + i] - g_dual[buf][2][b * NPTS + i];
        acc += g_dual[buf][1][b * NPTS + i] - g_dual[buf][3][b * NPTS + i];
    }
    __shared__ float red[256];
    red[tid] = acc;
    __syncthreads();
    for (int off = 128; off > 0; off >>= 1) {
        if (tid < off) red[tid] += red[tid + off];
        __syncthreads();
    }
    if (tid == 0) {
        float w = expf(-logf((float)NPTS));
        out[b] = red[0] * w;
    }
}

extern "C" void kernel_launch(void* const* d_in, const int* in_sizes, int n_in,
                              void* d_out, int out_size)
{
    const float* x = (const float*)d_in[0];
    const float* y = (const float*)d_in[1];
    float* out = (float*)d_out;

    // max smem carveout -> 6 resident blocks/SM instead of 3 (idempotent, cheap)
    cudaFuncSetAttribute(sinkhorn_phase,
                         cudaFuncAttributePreferredSharedMemoryCarveout, 100);

    dim3 grid(NPTS / TPB, 4, BATCH);

    // epsilon schedule: [diameter^2] + exp(arange(2ln2, 2ln0.05, 2ln0.5)) + [blur^2]
    const float eps_list[8] = {4.0f, 4.0f, 1.0f, 0.25f, 0.0625f,
                               0.015625f, 0.00390625f, 0.0025f};

    // init at eps0=4 (h = log-weights only), write buf0
    sinkhorn_phase<<<grid, TPB>>>(x, y, 4.0f, 0.0f, 0, 0, 0);

    int cur = 0;
    for (int i = 0; i < 8; i++) {
        sinkhorn_phase<<<grid, TPB>>>(x, y, eps_list[i], 1.0f, 1, cur, cur ^ 1);
        cur ^= 1;
    }
    // final extrapolation at blur^2, no averaging
    sinkhorn_phase<<<grid, TPB>>>(x, y, 0.0025f, 1.0f, 0, cur, cur ^ 1);
    cur ^= 1;

    sinkhorn_reduce<<<BATCH, 256>>>(out, cur);
}

// round 6
// speedup vs baseline: 1.3383x; 1.3233x over previous
#include <cuda_runtime.h>
#include <math.h>

#define BATCH 8
#define NPTS  2048
#define HCOLS 1024            // columns per block (half split)
#define LOG2E 1.4426950408889634f
#define LN2   0.6931471805599453f
#define TPB   128
#define CHUNK 16

// dual potentials, double-buffered: [buf][s: f_ba,g_ab,f_aa,g_bb][b*NPTS + i]
__device__ float g_dual[2][4][BATCH * NPTS];
// per-half partial LSE state: [half][s][b*NPTS + r], m in log2 units
__device__ float g_pm[2][4][BATCH * NPTS];
__device__ float g_ps[2][4][BATCH * NPTS];
// 0.5*|p|^2 per point, [0]=x rows, [1]=y rows
__device__ float g_sq[2][BATCH * NPTS];

__device__ __forceinline__ float ex2(float x) {
    float r;
    asm("ex2.approx.ftz.f32 %0, %1;" : "=f"(r) : "f"(x));
    return r;
}
__device__ __forceinline__ unsigned long long pk2(float a, float b) {
    unsigned long long u;
    asm("mov.b64 %0, {%1,%2};" : "=l"(u) : "f"(a), "f"(b));
    return u;
}
__device__ __forceinline__ void upk2(unsigned long long u, float& a, float& b) {
    asm("mov.b64 {%0,%1}, %2;" : "=f"(a), "=f"(b) : "l"(u));
}
__device__ __forceinline__ unsigned long long fma2(unsigned long long a,
                                                   unsigned long long b,
                                                   unsigned long long c) {
    unsigned long long d;
    asm("fma.rn.f32x2 %0, %1, %2, %3;" : "=l"(d) : "l"(a), "l"(b), "l"(c));
    return d;
}

// softmin(eps,C,h)_i = -eps * LSE_j( h_j - C_ij/eps ), C_ij = .5|r_i|^2+.5|c_j|^2 - r.c
// log2 domain: arg2_j = (h_j - .5|c_j|^2/eps)*log2e + r_i.c_j*(log2e/eps)
// This kernel computes a PARTIAL (max, sum) over a 1024-column half.
__global__ __launch_bounds__(TPB) void sinkhorn_phase(
    const float* __restrict__ x, const float* __restrict__ y,
    float eps, float dual_scale, int rbuf)
{
    const int s = blockIdx.y;
    const int b = blockIdx.z;
    const int half   = blockIdx.x & 1;
    const int rowblk = blockIdx.x >> 1;
    const float* rows = (s == 0 || s == 2) ? x : y;
    const float* cols = (s == 0 || s == 3) ? y : x;
    const int di = (s == 0) ? 1 : (s == 1) ? 0 : s;
    const float* dual = g_dual[rbuf][di] + b * NPTS;

    // pair-interleaved column table:
    // sh[2p]   = (c0a*sc, c0b*sc, c1a*sc, c1b*sc)
    // sh[2p+1] = (c2a*sc, c2b*sc, wa,     wb)      for columns (2p, 2p+1)
    __shared__ float4 sh[HCOLS];

    const float inv_eps = 1.0f / eps;
    const float sc = inv_eps * LOG2E;
    const float logw = -logf((float)NPTS);
    const int col0 = half * HCOLS;

    for (int p = threadIdx.x; p < HCOLS / 2; p += TPB) {
        int j = col0 + 2 * p;
        const float* c = cols + (b * NPTS + j) * 3;
        float c0a = c[0], c1a = c[1], c2a = c[2];
        float c0b = c[3], c1b = c[4], c2b = c[5];
        float ha = logw + dual_scale * dual[j] * inv_eps;
        float hb = logw + dual_scale * dual[j + 1] * inv_eps;
        float wa = (ha - 0.5f * (c0a * c0a + c1a * c1a + c2a * c2a) * inv_eps) * LOG2E;
        float wb = (hb - 0.5f * (c0b * c0b + c1b * c1b + c2b * c2b) * inv_eps) * LOG2E;
        sh[2 * p]     = make_float4(c0a * sc, c0b * sc, c1a * sc, c1b * sc);
        sh[2 * p + 1] = make_float4(c2a * sc, c2b * sc, wa, wb);
    }
    __syncthreads();

    const int r = rowblk * TPB + threadIdx.x;
    const float* xr = rows + (b * NPTS + r) * 3;
    const float x0 = xr[0], x1 = xr[1], x2 = xr[2];
    const unsigned long long X0 = pk2(x0, x0);
    const unsigned long long X1 = pk2(x1, x1);
    const unsigned long long X2 = pk2(x2, x2);

    const ulonglong2* shu = (const ulonglong2*)sh;

    float m = -INFINITY;
    float ssum = 0.0f;

    #pragma unroll 1
    for (int j = 0; j < HCOLS; j += CHUNK) {
        // packed dot products: 3 FFMA2 per column pair
        unsigned long long d[CHUNK / 2];
        #pragma unroll
        for (int k = 0; k < CHUNK / 2; k++) {
            ulonglong2 A = shu[j + 2 * k];
            ulonglong2 B = shu[j + 2 * k + 1];
            d[k] = fma2(X0, A.x, fma2(X1, A.y, fma2(X2, B.x, B.y)));
        }
        float a[CHUNK];
        #pragma unroll
        for (int k = 0; k < CHUNK / 2; k++) upk2(d[k], a[2 * k], a[2 * k + 1]);

        // chunk-local max tree
        float t0 = fmaxf(a[0], a[1]),   t1 = fmaxf(a[2], a[3]);
        float t2 = fmaxf(a[4], a[5]),   t3 = fmaxf(a[6], a[7]);
        float t4 = fmaxf(a[8], a[9]),   t5 = fmaxf(a[10], a[11]);
        float t6 = fmaxf(a[12], a[13]), t7 = fmaxf(a[14], a[15]);
        float u0 = fmaxf(t0, t1), u1 = fmaxf(t2, t3);
        float u2 = fmaxf(t4, t5), u3 = fmaxf(t6, t7);
        float cm = fmaxf(fmaxf(u0, u1), fmaxf(u2, u3));

        float e[CHUNK];
        #pragma unroll
        for (int k = 0; k < CHUNK; k++) e[k] = ex2(a[k] - cm);
        float s0 = (e[0] + e[1]) + (e[2] + e[3]);
        float s1 = (e[4] + e[5]) + (e[6] + e[7]);
        float s2 = (e[8] + e[9]) + (e[10] + e[11]);
        float s3 = (e[12] + e[13]) + (e[14] + e[15]);
        float csum = (s0 + s1) + (s2 + s3);

        // branchless merge
        float mn = fmaxf(m, cm);
        ssum = fmaf(ssum, ex2(m - mn), csum * ex2(cm - mn));
        m = mn;
    }

    g_pm[half][s][b * NPTS + r] = m;
    g_ps[half][s][b * NPTS + r] = ssum;
}

// merge the two column-halves, finish the softmin, apply averaging
__global__ void sinkhorn_combine(float eps, int do_avg, int rbuf, int wbuf)
{
    int idx = blockIdx.x * 256 + threadIdx.x;      // 4*BATCH*NPTS = 65536
    int s = idx >> 14;
    int rem = idx & 16383;                         // b*NPTS + r
    float m0 = g_pm[0][s][rem], m1 = g_pm[1][s][rem];
    float s0 = g_ps[0][s][rem], s1 = g_ps[1][s][rem];
    float mn = fmaxf(m0, m1);
    float sm = fmaf(s0, ex2(m0 - mn), s1 * ex2(m1 - mn));
    float lse = LN2 * (mn + log2f(sm));
    int rows_sel = (s == 0 || s == 2) ? 0 : 1;
    float fraw = -eps * lse + g_sq[rows_sel][rem];
    float o = do_avg ? 0.5f * (g_dual[rbuf][s][rem] + fraw) : fraw;
    g_dual[wbuf][s][rem] = o;
}

__global__ void init_sq(const float* __restrict__ x, const float* __restrict__ y)
{
    int idx = blockIdx.x * 256 + threadIdx.x;      // 2*BATCH*NPTS = 32768
    int sel = idx >> 14;
    int rem = idx & 16383;
    const float* p = (sel ? y : x) + rem * 3;
    g_sq[sel][rem] = 0.5f * (p[0] * p[0] + p[1] * p[1] + p[2] * p[2]);
}

// out[b] = (1/N) * sum_i (f_ba - f_aa) + (1/M) * sum_j (g_ab - g_bb)
__global__ void sinkhorn_reduce(float* __restrict__ out, int buf)
{
    const int b = blockIdx.x;
    const int tid = threadIdx.x;
    float acc = 0.0f;
    for (int i = tid; i < NPTS; i += 256) {
        acc += g_dual[buf][0][b * NPTS + i] - g_dual[buf][2][b * NPTS + i];
        acc += g_dual[buf][1][b * NPTS + i] - g_dual[buf][3][b * NPTS + i];
    }
    __shared__ float red[256];
    red[tid] = acc;
    __syncthreads();
    for (int off = 128; off > 0; off >>= 1) {
        if (tid < off) red[tid] += red[tid + off];
        __syncthreads();
    }
    if (tid == 0) {
        float w = expf(-logf((float)NPTS));
        out[b] = red[0] * w;
    }
}

extern "C" void kernel_launch(void* const* d_in, const int* in_sizes, int n_in,
                              void* d_out, int out_size)
{
    const float* x = (const float*)d_in[0];
    const float* y = (const float*)d_in[1];
    float* out = (float*)d_out;

    dim3 grid(2 * NPTS / TPB, 4, BATCH);   // (32, 4, 8) = 1024 blocks

    // epsilon schedule: [diameter^2] + exp(arange(2ln2, 2ln0.05, 2ln0.5)) + [blur^2]
    const float eps_list[8] = {4.0f, 4.0f, 1.0f, 0.25f, 0.0625f,
                               0.015625f, 0.00390625f, 0.0025f};

    init_sq<<<128, 256>>>(x, y);

    // init at eps0=4 (h = log-weights only) -> buf0
    sinkhorn_phase<<<grid, TPB>>>(x, y, 4.0f, 0.0f, 0);
    sinkhorn_combine<<<256, 256>>>(4.0f, 0, 0, 0);

    int cur = 0;
    for (int i = 0; i < 8; i++) {
        sinkhorn_phase<<<grid, TPB>>>(x, y, eps_list[i], 1.0f, cur);
        sinkhorn_combine<<<256, 256>>>(eps_list[i], 1, cur, cur ^ 1);
        cur ^= 1;
    }
    // final extrapolation at blur^2, no averaging
    sinkhorn_phase<<<grid, TPB>>>(x, y, 0.0025f, 1.0f, cur);
    sinkhorn_combine<<<256, 256>>>(0.0025f, 0, cur, cur ^ 1);
    cur ^= 1;

    sinkhorn_reduce<<<BATCH, 256>>>(out, cur);
}